// round 15
// baseline (speedup 1.0000x reference)
#include <cuda_runtime.h>
#include <cuda_fp16.h>
#include <cstdint>
#include <cstddef>

// ---------------------------------------------------------------------------
// Critic_Mix fused kernel (round 14): R13 base (128 thr, 2m x 2n warp grid of
// 32x64 tiles, 2 CTAs/SM, 256-reg budget) + packed __half2 mix accumulator
// (-32 regs) funding a FULL fragment double-buffer in the k-loop (+24 regs):
// all 6 LDSMs for j+1 issue before the 16 MMAs of j. Net ~245 regs.
// ---------------------------------------------------------------------------

#define THREADS   128
#define BM        64
#define BATCH     262144
#define NBLK      (BATCH / BM)

#define ACT_B      16384                 // 64 rows x 256B (128 fp16)
#define WBUF_B     32768                 // 128 rows x 256B fp16
#define WBUF_OFF   (5 * ACT_B)           // 81920
#define BIAS_OFF   (WBUF_OFF + WBUF_B)   // 114688
#define SMEM_BYTES (BIAS_OFF + 1024)     // 115712 -> 2 CTAs/SM

__device__ uint4 g_wimg[30 * 2048];
__device__ float g_bimg[30 * 128];

struct Params {
    const float* x;
    const float* u;
    const float* mixf;
    const float* P;
    const float* W[2][3];
    const float* Bb[2][3];
    const float* W4[2];
    const float* b4[2];
    const float* tW[2][3];
    const float* tb[2][3];
    float*       out;
};

__device__ __forceinline__ uint32_t s2u(const void* p) {
    uint32_t a;
    asm("{ .reg .u64 t; cvta.to.shared.u64 t, %1; cvt.u32.u64 %0, t; }"
        : "=r"(a) : "l"(p));
    return a;
}
__device__ __forceinline__ void ldsm4(uint32_t* r, uint32_t addr) {
    asm volatile("ldmatrix.sync.aligned.m8n8.x4.shared.b16 {%0,%1,%2,%3}, [%4];"
                 : "=r"(r[0]), "=r"(r[1]), "=r"(r[2]), "=r"(r[3]) : "r"(addr));
}
__device__ __forceinline__ void mma16(float* c, const uint32_t* a,
                                      uint32_t b0, uint32_t b1) {
    asm volatile(
        "mma.sync.aligned.m16n8k16.row.col.f32.f16.f16.f32 "
        "{%0,%1,%2,%3}, {%4,%5,%6,%7}, {%8,%9}, {%0,%1,%2,%3};"
        : "+f"(c[0]), "+f"(c[1]), "+f"(c[2]), "+f"(c[3])
        : "r"(a[0]), "r"(a[1]), "r"(a[2]), "r"(a[3]), "r"(b0), "r"(b1));
}
__device__ __forceinline__ void cpasync16(uint32_t dst, const void* src) {
    asm volatile("cp.async.cg.shared.global [%0], [%1], 16;"
                 :: "r"(dst), "l"(src) : "memory");
}

// ---------------- preprocessing kernel (R10 layout, proven) ----------------
__global__ void prep_kernel(Params p) {
    const int idx = blockIdx.x * 256 + threadIdx.x;
    if (idx < 30 * 2048) {
        const int img = idx >> 11, rem = idx & 2047;
        const int n = rem >> 4, ch = rem & 15;
        const int h = img / 15, rr = img % 15, L = rr / 5, s = rr % 5;
        const int O = (L == 2) ? 64 : 128;
        uint4 o = make_uint4(0u, 0u, 0u, 0u);
        if (n < O) {
            const float* W = (s == 4) ? p.W[h][L]
                                      : p.tW[h][L] + (size_t)s * O * 128;
            const float4 v0 = *reinterpret_cast<const float4*>(W + (size_t)n * 128 + ch * 8);
            const float4 v1 = *reinterpret_cast<const float4*>(W + (size_t)n * 128 + ch * 8 + 4);
            __half2 t0 = __floats2half2_rn(v0.x, v0.y);
            __half2 t1 = __floats2half2_rn(v0.z, v0.w);
            __half2 t2 = __floats2half2_rn(v1.x, v1.y);
            __half2 t3 = __floats2half2_rn(v1.z, v1.w);
            o.x = *reinterpret_cast<uint32_t*>(&t0);
            o.y = *reinterpret_cast<uint32_t*>(&t1);
            o.z = *reinterpret_cast<uint32_t*>(&t2);
            o.w = *reinterpret_cast<uint32_t*>(&t3);
        }
        g_wimg[img * 2048 + n * 16 + (ch ^ (n & 7))] = o;
    } else if (idx < 30 * 2048 + 960) {
        const int b = idx - 30 * 2048;
        const int img = b >> 5, q = b & 31;
        const int h = img / 15, rr = img % 15, L = rr / 5, s = rr % 5;
        const int O = (L == 2) ? 64 : 128;
        const float* B = (s == 4) ? p.Bb[h][L] : p.tb[h][L] + s * O;
        const int o = q * 4;
        float4 v;
        v.x = (o + 0 < O) ? B[o + 0] : 0.f;
        v.y = (o + 1 < O) ? B[o + 1] : 0.f;
        v.z = (o + 2 < O) ? B[o + 2] : 0.f;
        v.w = (o + 3 < O) ? B[o + 3] : 0.f;
        *reinterpret_cast<float4*>(g_bimg + img * 128 + o) = v;
    }
}

// ---------------- main kernel ----------------
__device__ __forceinline__ void prefetch_img(uint32_t wbuf_u, uint32_t bias_u,
                                             int img, int bslot, int tid) {
    const uint4* src = g_wimg + img * 2048;
    const int nv = (((img % 15) / 5) == 2) ? 8 : 16;   // L=2: 16KB only
    #pragma unroll
    for (int i = 0; i < 16; i++)
        if (i < nv)
            cpasync16(wbuf_u + (uint32_t)(tid + i * 128) * 16, src + tid + i * 128);
    if (tid < 32)
        cpasync16(bias_u + (uint32_t)bslot * 512 + tid * 16,
                  reinterpret_cast<const float4*>(g_bimg + img * 128) + tid);
    asm volatile("cp.async.commit_group;" ::: "memory");
}

__global__ void __launch_bounds__(THREADS, 2)
critic_main(Params p) {
    extern __shared__ char smem[];
    const uint32_t sbase  = s2u(smem);
    const uint32_t wbuf_u = sbase + WBUF_OFF;
    const uint32_t bias_u = sbase + BIAS_OFF;
    float* biasf = reinterpret_cast<float*>(smem + BIAS_OFF);

    const int tid  = threadIdx.x;
    const int lane = tid & 31;
    const int wid  = tid >> 5;          // 0..3
    const int wm   = wid & 1;           // 2 warps over m (32 rows each)
    const int wn   = wid >> 1;          // 2 warps over n (64 outputs each)
    const int mbase = wm * 32;
    const int nbase = wn * 64;
    const int lq = lane >> 2, lr = lane & 3;
    const int r8 = lane & 7, sel = lane >> 3;
    const int row0 = blockIdx.x * BM;
    const bool lowN = (wn == 0);

    const int rA0 = mbase + (sel & 1) * 8 + r8;
    const int rB0 = nbase + (sel >> 1) * 8 + r8;
    const uint32_t eA4 = (uint32_t)(((sel >> 1) ^ r8) << 4);
    const uint32_t eB4 = (uint32_t)(((sel & 1) ^ r8) << 4);
    const uint32_t aoff0 = (uint32_t)rA0 * 256;
    const uint32_t aoff1 = aoff0 + 16 * 256;
    uint32_t bbq[4];
    #pragma unroll
    for (int q = 0; q < 4; q++)
        bbq[q] = wbuf_u + (uint32_t)(rB0 + q * 16) * 256;

    const uint32_t rbase = (uint32_t)(mbase + lq) * 256;
    uint32_t coff[8];
    #pragma unroll
    for (int nt = 0; nt < 8; nt++)
        coff[nt] = ((uint32_t)((((nbase >> 3) + nt) ^ lq) << 4)) + (uint32_t)lr * 4;

    const float m = __ldg(p.mixf);
    const float inv_m = 1.0f - m;
    float Pk[4];
    #pragma unroll
    for (int k = 0; k < 4; k++) Pk[k] = __ldg(p.P + k);

    prefetch_img(wbuf_u, bias_u, 0, 0, tid);

    for (int h = 0; h < 2; h++) {
        // ---- xu -> act buffer 4 (fp16, swizzled) ----
        {
            char* dst = smem + 4 * ACT_B;
            #pragma unroll
            for (int i = tid; i < BM * 16; i += THREADS) {
                const int r = i >> 4, ch = i & 15;
                float4 v0, v1;
                if (ch < 12) {
                    const float* src = p.x + (size_t)(row0 + r) * 96 + ch * 8;
                    v0 = *reinterpret_cast<const float4*>(src);
                    v1 = *reinterpret_cast<const float4*>(src + 4);
                } else {
                    const float* src = p.u + (size_t)(row0 + r) * 32 + (ch - 12) * 8;
                    v0 = *reinterpret_cast<const float4*>(src);
                    v1 = *reinterpret_cast<const float4*>(src + 4);
                }
                __half2 t0 = __floats2half2_rn(v0.x, v0.y);
                __half2 t1 = __floats2half2_rn(v0.z, v0.w);
                __half2 t2 = __floats2half2_rn(v1.x, v1.y);
                __half2 t3 = __floats2half2_rn(v1.z, v1.w);
                uint4 o;
                o.x = *reinterpret_cast<uint32_t*>(&t0);
                o.y = *reinterpret_cast<uint32_t*>(&t1);
                o.z = *reinterpret_cast<uint32_t*>(&t2);
                o.w = *reinterpret_cast<uint32_t*>(&t3);
                *reinterpret_cast<uint4*>(dst + r * 256 + ((ch ^ (r & 7)) << 4)) = o;
            }
        }

        __half2 mix2[2][8][2];               // packed mix accumulator (32 regs)
        for (int t = 0; t < 15; t++) {
            const int g = h * 15 + t;
            const int L = t / 5, s = t % 5;
            const bool is_main = (s == 4);
            const bool active  = (L < 2) || lowN;
            if (s == 0) {
                const __half2 z = __floats2half2_rn(0.f, 0.f);
                #pragma unroll
                for (int mt = 0; mt < 2; mt++)
                    #pragma unroll
                    for (int nt = 0; nt < 8; nt++) {
                        mix2[mt][nt][0] = z; mix2[mt][nt][1] = z;
                    }
            }

            asm volatile("cp.async.wait_group 0;" ::: "memory");
            __syncthreads();

            float acc[2][8][4];
            #pragma unroll
            for (int mt = 0; mt < 2; mt++)
                #pragma unroll
                for (int nt = 0; nt < 8; nt++)
                    #pragma unroll
                    for (int c = 0; c < 4; c++) acc[mt][nt][c] = 0.f;

            if (active) {
                const int inb = (L == 0) ? 4 : (is_main ? 4 : s);
                const uint32_t ab0 = sbase + (uint32_t)inb * ACT_B + aoff0;
                const uint32_t ab1 = sbase + (uint32_t)inb * ACT_B + aoff1;

                // full fragment double-buffer: 6 LDSMs of j+1 before MMAs of j
                uint32_t fa0[2][4], fa1[2][4], fb[2][4][4];
                ldsm4(fa0[0], ab0 + eA4);
                ldsm4(fa1[0], ab1 + eA4);
                #pragma unroll
                for (int q = 0; q < 4; q++)
                    ldsm4(fb[0][q], bbq[q] + eB4);
                #pragma unroll
                for (int j = 0; j < 8; j++) {
                    const int cur = j & 1, nxt = cur ^ 1;
                    if (j < 7) {
                        const uint32_t tA = ((uint32_t)((j + 1) << 5)) ^ eA4;
                        const uint32_t tB = ((uint32_t)((j + 1) << 5)) ^ eB4;
                        ldsm4(fa0[nxt], ab0 + tA);
                        ldsm4(fa1[nxt], ab1 + tA);
                        #pragma unroll
                        for (int q = 0; q < 4; q++)
                            ldsm4(fb[nxt][q], bbq[q] + tB);
                    }
                    #pragma unroll
                    for (int q = 0; q < 4; q++) {
                        mma16(acc[0][2 * q + 0], fa0[cur], fb[cur][q][0], fb[cur][q][1]);
                        mma16(acc[0][2 * q + 1], fa0[cur], fb[cur][q][2], fb[cur][q][3]);
                        mma16(acc[1][2 * q + 0], fa1[cur], fb[cur][q][0], fb[cur][q][1]);
                        mma16(acc[1][2 * q + 1], fa1[cur], fb[cur][q][2], fb[cur][q][3]);
                    }
                }
            }

            // bias for THIS stream (slot g&1 stable since top barrier)
            float bias[8][2];
            {
                const float* bs = biasf + (g & 1) * 128;
                #pragma unroll
                for (int nt = 0; nt < 8; nt++) {
                    bias[nt][0] = bs[nbase + nt * 8 + lr * 2 + 0];
                    bias[nt][1] = bs[nbase + nt * 8 + lr * 2 + 1];
                }
            }

            __syncthreads();    // wbuf + act reads done

            prefetch_img(wbuf_u, bias_u, (g + 1) % 30, (g + 1) & 1, tid);

            if (active) {
                const float sc = is_main ? inv_m : (m * Pk[s]);
                const bool do_store = is_main || (L < 2);
                char* outb = smem + (is_main ? 4 : s) * ACT_B;
                #pragma unroll
                for (int mt = 0; mt < 2; mt++)
                    #pragma unroll
                    for (int nt = 0; nt < 8; nt++)
                        #pragma unroll
                        for (int c2 = 0; c2 < 2; c2++) {
                            const float v0 = acc[mt][nt][c2 * 2 + 0] + bias[nt][0];
                            const float v1 = acc[mt][nt][c2 * 2 + 1] + bias[nt][1];
                            float o0, o1;
                            if (!is_main) {
                                float2 mf = __half22float2(mix2[mt][nt][c2]);
                                mf.x = fmaf(sc, v0, mf.x);
                                mf.y = fmaf(sc, v1, mf.y);
                                mix2[mt][nt][c2] = __floats2half2_rn(mf.x, mf.y);
                                o0 = v0; o1 = v1;
                            } else {
                                o0 = fmaf(sc, v0, __low2float(mix2[mt][nt][c2]));
                                o1 = fmaf(sc, v1, __high2float(mix2[mt][nt][c2]));
                            }
                            if (do_store) {
                                __half2 hv = __floats2half2_rn(fmaxf(o0, 0.f),
                                                               fmaxf(o1, 0.f));
                                *reinterpret_cast<uint32_t*>(
                                    outb + rbase + mt * 4096 + c2 * 2048 + coff[nt])
                                    = *reinterpret_cast<uint32_t*>(&hv);
                            }
                        }
            }
        }

        __syncthreads();
        // ---- final layer: out = h3 . W4 + b4 ----
        if (tid < BM) {
            float sum = __ldg(p.b4[h]);
            const float* W4 = p.W4[h];
            const char* hb = smem + 4 * ACT_B;
            #pragma unroll
            for (int k2 = 0; k2 < 64; k2++) {
                const __half hv = *reinterpret_cast<const __half*>(
                    hb + tid * 256 + (((k2 >> 3) ^ (tid & 7)) << 4) + (k2 & 7) * 2);
                sum = fmaf(__half2float(hv), __ldg(W4 + k2), sum);
            }
            p.out[(size_t)h * BATCH + row0 + tid] = sum;
        }
        __syncthreads();
    }
}

extern "C" void kernel_launch(void* const* d_in, const int* in_sizes, int n_in,
                              void* d_out, int out_size) {
    (void)in_sizes; (void)n_in; (void)out_size;
    Params p;
    p.x    = (const float*)d_in[0];
    p.u    = (const float*)d_in[1];
    p.mixf = (const float*)d_in[2];
    p.P    = (const float*)d_in[3];
    for (int h = 0; h < 2; h++) {
        const int base = 4 + h * 8;
        p.W[h][0]  = (const float*)d_in[base + 0];
        p.Bb[h][0] = (const float*)d_in[base + 1];
        p.W[h][1]  = (const float*)d_in[base + 2];
        p.Bb[h][1] = (const float*)d_in[base + 3];
        p.W[h][2]  = (const float*)d_in[base + 4];
        p.Bb[h][2] = (const float*)d_in[base + 5];
        p.W4[h]    = (const float*)d_in[base + 6];
        p.b4[h]    = (const float*)d_in[base + 7];
        const int tbase = 20 + h * 6;
        p.tW[h][0] = (const float*)d_in[tbase + 0];
        p.tb[h][0] = (const float*)d_in[tbase + 1];
        p.tW[h][1] = (const float*)d_in[tbase + 2];
        p.tb[h][1] = (const float*)d_in[tbase + 3];
        p.tW[h][2] = (const float*)d_in[tbase + 4];
        p.tb[h][2] = (const float*)d_in[tbase + 5];
    }
    p.out = (float*)d_out;

    prep_kernel<<<(30 * 2048 + 960 + 255) / 256, 256>>>(p);
    cudaFuncSetAttribute(critic_main,
                         cudaFuncAttributeMaxDynamicSharedMemorySize, SMEM_BYTES);
    critic_main<<<NBLK, THREADS, SMEM_BYTES>>>(p);
}

// round 16
// speedup vs baseline: 1.0137x; 1.0137x over previous
#include <cuda_runtime.h>
#include <cuda_fp16.h>
#include <cstdint>
#include <cstddef>

// ---------------------------------------------------------------------------
// Critic_Mix fused kernel (round 15): R10 base (fp16 m16n8k16, BM=64, 256 thr,
// 2m x 4n warp grid, 2 CTAs/SM) + HALF-K double-buffered weight fetch:
// each 32KB image split into two 16KB k-halves (s0=h1, s1=h2). Fetch(t).h2
// overlaps k-half1(t); fetch(t+1).h1 overlaps k-half2(t)+epilogue. Every
// cp.async now has >= half-a-k-loop of cover. 3 barriers/stream.
// ---------------------------------------------------------------------------

#define THREADS   256
#define BM        64
#define BATCH     262144
#define NBLK      (BATCH / BM)

#define ACT_B      16384                 // 64 rows x 256B (128 fp16)
#define WHALF_B    16384                 // 128 rows x 128B (64 fp16 k-half)
#define WBUF_OFF   (5 * ACT_B)           // 81920  (s0 @ +0, s1 @ +16384)
#define BIAS_OFF   (WBUF_OFF + 2 * WHALF_B)  // 114688
#define SMEM_BYTES (BIAS_OFF + 1024)     // 115712 -> 2 CTAs/SM

// Weight image, half-k layout: img = 2 halves x 16KB.
// half H covers k in [H*64, H*64+64). uint4 index within img:
//   H*1024 + n*8 + (ch ^ (n & 7)),  n = output row 0..127, ch = 0..7
//   (16B chunk ch covers k elements H*64 + ch*8 .. +8)
// O=64 images: rows 64..127 zero; valid data = first 8KB of each half.
__device__ uint4 g_wimg[30 * 2048];
__device__ float g_bimg[30 * 128];

struct Params {
    const float* x;
    const float* u;
    const float* mixf;
    const float* P;
    const float* W[2][3];
    const float* Bb[2][3];
    const float* W4[2];
    const float* b4[2];
    const float* tW[2][3];
    const float* tb[2][3];
    float*       out;
};

__device__ __forceinline__ uint32_t s2u(const void* p) {
    uint32_t a;
    asm("{ .reg .u64 t; cvta.to.shared.u64 t, %1; cvt.u32.u64 %0, t; }"
        : "=r"(a) : "l"(p));
    return a;
}
__device__ __forceinline__ void ldsm4(uint32_t* r, uint32_t addr) {
    asm volatile("ldmatrix.sync.aligned.m8n8.x4.shared.b16 {%0,%1,%2,%3}, [%4];"
                 : "=r"(r[0]), "=r"(r[1]), "=r"(r[2]), "=r"(r[3]) : "r"(addr));
}
__device__ __forceinline__ void mma16(float* c, const uint32_t* a,
                                      uint32_t b0, uint32_t b1) {
    asm volatile(
        "mma.sync.aligned.m16n8k16.row.col.f32.f16.f16.f32 "
        "{%0,%1,%2,%3}, {%4,%5,%6,%7}, {%8,%9}, {%0,%1,%2,%3};"
        : "+f"(c[0]), "+f"(c[1]), "+f"(c[2]), "+f"(c[3])
        : "r"(a[0]), "r"(a[1]), "r"(a[2]), "r"(a[3]), "r"(b0), "r"(b1));
}
__device__ __forceinline__ void cpasync16(uint32_t dst, const void* src) {
    asm volatile("cp.async.cg.shared.global [%0], [%1], 16;"
                 :: "r"(dst), "l"(src) : "memory");
}

// ---------------- preprocessing kernel ----------------
__global__ void prep_kernel(Params p) {
    const int idx = blockIdx.x * 256 + threadIdx.x;
    if (idx < 30 * 2048) {
        const int img  = idx >> 11;
        const int rem  = idx & 2047;
        const int half = rem >> 10;
        const int wi   = rem & 1023;
        const int n    = wi >> 3;
        const int ch   = wi & 7;
        const int h = img / 15, rr = img % 15, L = rr / 5, s = rr % 5;
        const int O = (L == 2) ? 64 : 128;
        uint4 o = make_uint4(0u, 0u, 0u, 0u);
        if (n < O) {
            const float* W = (s == 4) ? p.W[h][L]
                                      : p.tW[h][L] + (size_t)s * O * 128;
            const int k0 = half * 64 + ch * 8;
            const float4 v0 = *reinterpret_cast<const float4*>(W + (size_t)n * 128 + k0);
            const float4 v1 = *reinterpret_cast<const float4*>(W + (size_t)n * 128 + k0 + 4);
            __half2 t0 = __floats2half2_rn(v0.x, v0.y);
            __half2 t1 = __floats2half2_rn(v0.z, v0.w);
            __half2 t2 = __floats2half2_rn(v1.x, v1.y);
            __half2 t3 = __floats2half2_rn(v1.z, v1.w);
            o.x = *reinterpret_cast<uint32_t*>(&t0);
            o.y = *reinterpret_cast<uint32_t*>(&t1);
            o.z = *reinterpret_cast<uint32_t*>(&t2);
            o.w = *reinterpret_cast<uint32_t*>(&t3);
        }
        g_wimg[img * 2048 + half * 1024 + n * 8 + (ch ^ (n & 7))] = o;
    } else if (idx < 30 * 2048 + 960) {
        const int b = idx - 30 * 2048;
        const int img = b >> 5, q = b & 31;
        const int h = img / 15, rr = img % 15, L = rr / 5, s = rr % 5;
        const int O = (L == 2) ? 64 : 128;
        const float* B = (s == 4) ? p.Bb[h][L] : p.tb[h][L] + s * O;
        const int o = q * 4;
        float4 v;
        v.x = (o + 0 < O) ? B[o + 0] : 0.f;
        v.y = (o + 1 < O) ? B[o + 1] : 0.f;
        v.z = (o + 2 < O) ? B[o + 2] : 0.f;
        v.w = (o + 3 < O) ? B[o + 3] : 0.f;
        *reinterpret_cast<float4*>(g_bimg + img * 128 + o) = v;
    }
}

// ---------------- main kernel ----------------
// Fetch one 16KB k-half of image img into slot (s0 for half 0, s1 for half 1).
// half 0 also fetches the bias into bslot.
__device__ __forceinline__ void prefetch_half(uint32_t wbuf_u, uint32_t bias_u,
                                              int img, int half, int bslot,
                                              int tid) {
    const uint4* src = g_wimg + img * 2048 + half * 1024;
    const int nv = (((img % 15) / 5) == 2) ? 2 : 4;   // L=2: first 8KB only
    const uint32_t dst = wbuf_u + (uint32_t)half * WHALF_B;
    #pragma unroll
    for (int i = 0; i < 4; i++)
        if (i < nv)
            cpasync16(dst + (uint32_t)(tid + i * 256) * 16, src + tid + i * 256);
    if (half == 0 && tid < 32)
        cpasync16(bias_u + (uint32_t)bslot * 512 + tid * 16,
                  reinterpret_cast<const float4*>(g_bimg + img * 128) + tid);
    asm volatile("cp.async.commit_group;" ::: "memory");
}

__global__ void __launch_bounds__(THREADS, 2)
critic_main(Params p) {
    extern __shared__ char smem[];
    const uint32_t sbase  = s2u(smem);
    const uint32_t wbuf_u = sbase + WBUF_OFF;
    const uint32_t bias_u = sbase + BIAS_OFF;
    float* biasf = reinterpret_cast<float*>(smem + BIAS_OFF);

    const int tid  = threadIdx.x;
    const int lane = tid & 31;
    const int wid  = tid >> 5;
    const int wm   = wid & 1;           // 2 warps over m
    const int wn   = wid >> 1;          // 4 warps over n
    const int mbase = wm * 32;
    const int nbase = wn * 32;
    const int lq = lane >> 2, lr = lane & 3;
    const int r8 = lane & 7, sel = lane >> 3;
    const int row0 = blockIdx.x * BM;
    const bool lowN = (wn < 2);

    const int rA0 = mbase + (sel & 1) * 8 + r8;
    const int rB0 = nbase + (sel >> 1) * 8 + r8;
    const uint32_t eA4 = (uint32_t)(((sel >> 1) ^ r8) << 4);
    const uint32_t eB4 = (uint32_t)(((sel & 1) ^ r8) << 4);
    const uint32_t aoff0 = (uint32_t)rA0 * 256;
    const uint32_t aoff1 = aoff0 + 16 * 256;
    // B addressing inside a 16KB half: 128B rows
    const uint32_t bro0 = (uint32_t)rB0 * 128;
    const uint32_t bro1 = bro0 + 16 * 128;

    // epilogue store addressing (row&7 == lq)
    const uint32_t rbase = (uint32_t)(mbase + lq) * 256;
    uint32_t coff[4];
    #pragma unroll
    for (int nt = 0; nt < 4; nt++)
        coff[nt] = ((uint32_t)((((nbase >> 3) + nt) ^ lq) << 4)) + (uint32_t)lr * 4;

    const float m = __ldg(p.mixf);
    const float inv_m = 1.0f - m;
    float Pk[4];
    #pragma unroll
    for (int k = 0; k < 4; k++) Pk[k] = __ldg(p.P + k);

    prefetch_half(wbuf_u, bias_u, 0, 0, 0, tid);   // prime: stream 0 half 1

    for (int h = 0; h < 2; h++) {
        // ---- xu -> act buffer 4 (fp16, swizzled) ----
        {
            char* dst = smem + 4 * ACT_B;
            #pragma unroll
            for (int i = tid; i < BM * 16; i += THREADS) {
                const int r = i >> 4, ch = i & 15;
                float4 v0, v1;
                if (ch < 12) {
                    const float* src = p.x + (size_t)(row0 + r) * 96 + ch * 8;
                    v0 = *reinterpret_cast<const float4*>(src);
                    v1 = *reinterpret_cast<const float4*>(src + 4);
                } else {
                    const float* src = p.u + (size_t)(row0 + r) * 32 + (ch - 12) * 8;
                    v0 = *reinterpret_cast<const float4*>(src);
                    v1 = *reinterpret_cast<const float4*>(src + 4);
                }
                __half2 t0 = __floats2half2_rn(v0.x, v0.y);
                __half2 t1 = __floats2half2_rn(v0.z, v0.w);
                __half2 t2 = __floats2half2_rn(v1.x, v1.y);
                __half2 t3 = __floats2half2_rn(v1.z, v1.w);
                uint4 o;
                o.x = *reinterpret_cast<uint32_t*>(&t0);
                o.y = *reinterpret_cast<uint32_t*>(&t1);
                o.z = *reinterpret_cast<uint32_t*>(&t2);
                o.w = *reinterpret_cast<uint32_t*>(&t3);
                *reinterpret_cast<uint4*>(dst + r * 256 + ((ch ^ (r & 7)) << 4)) = o;
            }
        }

        float mix[2][4][4];
        for (int t = 0; t < 15; t++) {
            const int g = h * 15 + t;
            const int L = t / 5, s = t % 5;
            const bool is_main = (s == 4);
            const bool active  = (L < 2) || lowN;
            if (s == 0) {
                #pragma unroll
                for (int mt = 0; mt < 2; mt++)
                    #pragma unroll
                    for (int nt = 0; nt < 4; nt++)
                        #pragma unroll
                        for (int c = 0; c < 4; c++) mix[mt][nt][c] = 0.f;
            }

            // B1: half1 (s0) of this stream ready & visible; prev epilogue done
            asm volatile("cp.async.wait_group 0;" ::: "memory");
            __syncthreads();

            // launch half2 of THIS stream (s1 free since last stream's B3)
            prefetch_half(wbuf_u, bias_u, g, 1, 0, tid);

            float acc[2][4][4];
            #pragma unroll
            for (int mt = 0; mt < 2; mt++)
                #pragma unroll
                for (int nt = 0; nt < 4; nt++)
                    #pragma unroll
                    for (int c = 0; c < 4; c++) acc[mt][nt][c] = 0.f;

            const int inb = (L == 0) ? 4 : (is_main ? 4 : s);
            const uint32_t ab0 = sbase + (uint32_t)inb * ACT_B + aoff0;
            const uint32_t ab1 = sbase + (uint32_t)inb * ACT_B + aoff1;

            // ---- k half 1 (j = 0..3) reading s0 ----
            if (active) {
                const uint32_t bb0 = wbuf_u + bro0;
                const uint32_t bb1 = wbuf_u + bro1;
                #pragma unroll
                for (int j = 0; j < 4; j++) {
                    const uint32_t tA = ((uint32_t)(j << 5)) ^ eA4;
                    const uint32_t tB = ((uint32_t)(j << 5)) ^ eB4;
                    uint32_t fa0[4], fa1[4], fb0[4], fb1[4];
                    ldsm4(fa0, ab0 + tA);
                    ldsm4(fa1, ab1 + tA);
                    ldsm4(fb0, bb0 + tB);
                    ldsm4(fb1, bb1 + tB);
                    mma16(acc[0][0], fa0, fb0[0], fb0[1]);
                    mma16(acc[0][1], fa0, fb0[2], fb0[3]);
                    mma16(acc[0][2], fa0, fb1[0], fb1[1]);
                    mma16(acc[0][3], fa0, fb1[2], fb1[3]);
                    mma16(acc[1][0], fa1, fb0[0], fb0[1]);
                    mma16(acc[1][1], fa1, fb0[2], fb0[3]);
                    mma16(acc[1][2], fa1, fb1[0], fb1[1]);
                    mma16(acc[1][3], fa1, fb1[2], fb1[3]);
                }
            }

            // B2: half2 ready & visible; s0 reads done in all warps
            asm volatile("cp.async.wait_group 0;" ::: "memory");
            __syncthreads();

            // launch half1 of NEXT stream into s0 (+ its bias)
            prefetch_half(wbuf_u, bias_u, (g + 1) % 30, 0, (g + 1) & 1, tid);

            // ---- k half 2 (j = 4..7) reading s1 ----
            if (active) {
                const uint32_t bb0 = wbuf_u + WHALF_B + bro0;
                const uint32_t bb1 = wbuf_u + WHALF_B + bro1;
                #pragma unroll
                for (int j = 0; j < 4; j++) {
                    const uint32_t tA = ((uint32_t)((j + 4) << 5)) ^ eA4;
                    const uint32_t tB = ((uint32_t)(j << 5)) ^ eB4;
                    uint32_t fa0[4], fa1[4], fb0[4], fb1[4];
                    ldsm4(fa0, ab0 + tA);
                    ldsm4(fa1, ab1 + tA);
                    ldsm4(fb0, bb0 + tB);
                    ldsm4(fb1, bb1 + tB);
                    mma16(acc[0][0], fa0, fb0[0], fb0[1]);
                    mma16(acc[0][1], fa0, fb0[2], fb0[3]);
                    mma16(acc[0][2], fa0, fb1[0], fb1[1]);
                    mma16(acc[0][3], fa0, fb1[2], fb1[3]);
                    mma16(acc[1][0], fa1, fb0[0], fb0[1]);
                    mma16(acc[1][1], fa1, fb0[2], fb0[3]);
                    mma16(acc[1][2], fa1, fb1[0], fb1[1]);
                    mma16(acc[1][3], fa1, fb1[2], fb1[3]);
                }
            }

            // bias for THIS stream (slot g&1 stable since B1)
            float bias[4][2];
            {
                const float* bs = biasf + (g & 1) * 128;
                #pragma unroll
                for (int nt = 0; nt < 4; nt++) {
                    bias[nt][0] = bs[nbase + nt * 8 + lr * 2 + 0];
                    bias[nt][1] = bs[nbase + nt * 8 + lr * 2 + 1];
                }
            }

            // B3: act (and s1) reads done -> epilogue may overwrite act
            __syncthreads();

            if (active) {
                const float sc = is_main ? inv_m : (m * Pk[s]);
                const bool do_store = is_main || (L < 2);
                char* outb = smem + (is_main ? 4 : s) * ACT_B;
                #pragma unroll
                for (int mt = 0; mt < 2; mt++)
                    #pragma unroll
                    for (int nt = 0; nt < 4; nt++)
                        #pragma unroll
                        for (int c2 = 0; c2 < 2; c2++) {
                            const float v0 = acc[mt][nt][c2 * 2 + 0] + bias[nt][0];
                            const float v1 = acc[mt][nt][c2 * 2 + 1] + bias[nt][1];
                            float o0, o1;
                            if (!is_main) {
                                mix[mt][nt][c2 * 2 + 0] = fmaf(sc, v0, mix[mt][nt][c2 * 2 + 0]);
                                mix[mt][nt][c2 * 2 + 1] = fmaf(sc, v1, mix[mt][nt][c2 * 2 + 1]);
                                o0 = v0; o1 = v1;
                            } else {
                                o0 = fmaf(sc, v0, mix[mt][nt][c2 * 2 + 0]);
                                o1 = fmaf(sc, v1, mix[mt][nt][c2 * 2 + 1]);
                            }
                            if (do_store) {
                                __half2 hv = __floats2half2_rn(fmaxf(o0, 0.f),
                                                               fmaxf(o1, 0.f));
                                *reinterpret_cast<uint32_t*>(
                                    outb + rbase + mt * 4096 + c2 * 2048 + coff[nt])
                                    = *reinterpret_cast<uint32_t*>(&hv);
                            }
                        }
            }
        }

        __syncthreads();
        // ---- final layer: out = h3 . W4 + b4 ----
        if (tid < BM) {
            float sum = __ldg(p.b4[h]);
            const float* W4 = p.W4[h];
            const char* hb = smem + 4 * ACT_B;
            #pragma unroll
            for (int k2 = 0; k2 < 64; k2++) {
                const __half hv = *reinterpret_cast<const __half*>(
                    hb + tid * 256 + (((k2 >> 3) ^ (tid & 7)) << 4) + (k2 & 7) * 2);
                sum = fmaf(__half2float(hv), __ldg(W4 + k2), sum);
            }
            p.out[(size_t)h * BATCH + row0 + tid] = sum;
        }
        __syncthreads();
    }
}

extern "C" void kernel_launch(void* const* d_in, const int* in_sizes, int n_in,
                              void* d_out, int out_size) {
    (void)in_sizes; (void)n_in; (void)out_size;
    Params p;
    p.x    = (const float*)d_in[0];
    p.u    = (const float*)d_in[1];
    p.mixf = (const float*)d_in[2];
    p.P    = (const float*)d_in[3];
    for (int h = 0; h < 2; h++) {
        const int base = 4 + h * 8;
        p.W[h][0]  = (const float*)d_in[base + 0];
        p.Bb[h][0] = (const float*)d_in[base + 1];
        p.W[h][1]  = (const float*)d_in[base + 2];
        p.Bb[h][1] = (const float*)d_in[base + 3];
        p.W[h][2]  = (const float*)d_in[base + 4];
        p.Bb[h][2] = (const float*)d_in[base + 5];
        p.W4[h]    = (const float*)d_in[base + 6];
        p.b4[h]    = (const float*)d_in[base + 7];
        const int tbase = 20 + h * 6;
        p.tW[h][0] = (const float*)d_in[tbase + 0];
        p.tb[h][0] = (const float*)d_in[tbase + 1];
        p.tW[h][1] = (const float*)d_in[tbase + 2];
        p.tb[h][1] = (const float*)d_in[tbase + 3];
        p.tW[h][2] = (const float*)d_in[tbase + 4];
        p.tb[h][2] = (const float*)d_in[tbase + 5];
    }
    p.out = (float*)d_out;

    prep_kernel<<<(30 * 2048 + 960 + 255) / 256, 256>>>(p);
    cudaFuncSetAttribute(critic_main,
                         cudaFuncAttributeMaxDynamicSharedMemorySize, SMEM_BYTES);
    critic_main<<<NBLK, THREADS, SMEM_BYTES>>>(p);
}

// round 17
// speedup vs baseline: 1.0935x; 1.0787x over previous
#include <cuda_runtime.h>
#include <cuda_fp16.h>
#include <cstdint>
#include <cstddef>

// ---------------------------------------------------------------------------
// Critic_Mix fused kernel (round 16): R10 base (fp16 m16n8k16, BM=64, 256 thr,
// 2 CTAs/SM, single wbuf + cp.async next-stream prefetch) + L=2 warp-grid
// remap: O=64 layers run a 4m x 2n grid (16 rows x 32 outputs per warp) so
// ALL 8 warps work (R10 idled half). Same traffic, same barriers, same math
// order -> bit-identical results; per-warp k-chain halves on L=2 streams.
// ---------------------------------------------------------------------------

#define THREADS   256
#define BM        64
#define BATCH     262144
#define NBLK      (BATCH / BM)

#define ACT_B      16384                 // 64 rows x 256B (128 fp16)
#define WBUF_B     32768                 // 128 rows x 256B fp16
#define WBUF_OFF   (5 * ACT_B)           // 81920
#define BIAS_OFF   (WBUF_OFF + WBUF_B)   // 114688
#define SMEM_BYTES (BIAS_OFF + 1024)     // 115712 -> 2 CTAs/SM

__device__ uint4 g_wimg[30 * 2048];
__device__ float g_bimg[30 * 128];

struct Params {
    const float* x;
    const float* u;
    const float* mixf;
    const float* P;
    const float* W[2][3];
    const float* Bb[2][3];
    const float* W4[2];
    const float* b4[2];
    const float* tW[2][3];
    const float* tb[2][3];
    float*       out;
};

__device__ __forceinline__ uint32_t s2u(const void* p) {
    uint32_t a;
    asm("{ .reg .u64 t; cvta.to.shared.u64 t, %1; cvt.u32.u64 %0, t; }"
        : "=r"(a) : "l"(p));
    return a;
}
__device__ __forceinline__ void ldsm4(uint32_t* r, uint32_t addr) {
    asm volatile("ldmatrix.sync.aligned.m8n8.x4.shared.b16 {%0,%1,%2,%3}, [%4];"
                 : "=r"(r[0]), "=r"(r[1]), "=r"(r[2]), "=r"(r[3]) : "r"(addr));
}
__device__ __forceinline__ void mma16(float* c, const uint32_t* a,
                                      uint32_t b0, uint32_t b1) {
    asm volatile(
        "mma.sync.aligned.m16n8k16.row.col.f32.f16.f16.f32 "
        "{%0,%1,%2,%3}, {%4,%5,%6,%7}, {%8,%9}, {%0,%1,%2,%3};"
        : "+f"(c[0]), "+f"(c[1]), "+f"(c[2]), "+f"(c[3])
        : "r"(a[0]), "r"(a[1]), "r"(a[2]), "r"(a[3]), "r"(b0), "r"(b1));
}
__device__ __forceinline__ void cpasync16(uint32_t dst, const void* src) {
    asm volatile("cp.async.cg.shared.global [%0], [%1], 16;"
                 :: "r"(dst), "l"(src) : "memory");
}

// ---------------- preprocessing kernel (R10 layout, proven) ----------------
__global__ void prep_kernel(Params p) {
    const int idx = blockIdx.x * 256 + threadIdx.x;
    if (idx < 30 * 2048) {
        const int img = idx >> 11, rem = idx & 2047;
        const int n = rem >> 4, ch = rem & 15;
        const int h = img / 15, rr = img % 15, L = rr / 5, s = rr % 5;
        const int O = (L == 2) ? 64 : 128;
        uint4 o = make_uint4(0u, 0u, 0u, 0u);
        if (n < O) {
            const float* W = (s == 4) ? p.W[h][L]
                                      : p.tW[h][L] + (size_t)s * O * 128;
            const float4 v0 = *reinterpret_cast<const float4*>(W + (size_t)n * 128 + ch * 8);
            const float4 v1 = *reinterpret_cast<const float4*>(W + (size_t)n * 128 + ch * 8 + 4);
            __half2 t0 = __floats2half2_rn(v0.x, v0.y);
            __half2 t1 = __floats2half2_rn(v0.z, v0.w);
            __half2 t2 = __floats2half2_rn(v1.x, v1.y);
            __half2 t3 = __floats2half2_rn(v1.z, v1.w);
            o.x = *reinterpret_cast<uint32_t*>(&t0);
            o.y = *reinterpret_cast<uint32_t*>(&t1);
            o.z = *reinterpret_cast<uint32_t*>(&t2);
            o.w = *reinterpret_cast<uint32_t*>(&t3);
        }
        g_wimg[img * 2048 + n * 16 + (ch ^ (n & 7))] = o;
    } else if (idx < 30 * 2048 + 960) {
        const int b = idx - 30 * 2048;
        const int img = b >> 5, q = b & 31;
        const int h = img / 15, rr = img % 15, L = rr / 5, s = rr % 5;
        const int O = (L == 2) ? 64 : 128;
        const float* B = (s == 4) ? p.Bb[h][L] : p.tb[h][L] + s * O;
        const int o = q * 4;
        float4 v;
        v.x = (o + 0 < O) ? B[o + 0] : 0.f;
        v.y = (o + 1 < O) ? B[o + 1] : 0.f;
        v.z = (o + 2 < O) ? B[o + 2] : 0.f;
        v.w = (o + 3 < O) ? B[o + 3] : 0.f;
        *reinterpret_cast<float4*>(g_bimg + img * 128 + o) = v;
    }
}

// ---------------- main kernel ----------------
__device__ __forceinline__ void prefetch_img(uint32_t wbuf_u, uint32_t bias_u,
                                             int img, int bslot, int tid) {
    const uint4* src = g_wimg + img * 2048;
    const int nv = (((img % 15) / 5) == 2) ? 4 : 8;   // L=2: 16KB only
    #pragma unroll
    for (int i = 0; i < 8; i++)
        if (i < nv)
            cpasync16(wbuf_u + (uint32_t)(tid + i * 256) * 16, src + tid + i * 256);
    if (tid < 32)
        cpasync16(bias_u + (uint32_t)bslot * 512 + tid * 16,
                  reinterpret_cast<const float4*>(g_bimg + img * 128) + tid);
    asm volatile("cp.async.commit_group;" ::: "memory");
}

__global__ void __launch_bounds__(THREADS, 2)
critic_main(Params p) {
    extern __shared__ char smem[];
    const uint32_t sbase  = s2u(smem);
    const uint32_t wbuf_u = sbase + WBUF_OFF;
    const uint32_t bias_u = sbase + BIAS_OFF;
    float* biasf = reinterpret_cast<float*>(smem + BIAS_OFF);

    const int tid  = threadIdx.x;
    const int lane = tid & 31;
    const int wid  = tid >> 5;
    const int wm   = wid & 1;           // L<2 grid: 2 warps over m
    const int wn   = wid >> 1;          // L<2 grid: 4 warps over n
    const int mbase = wm * 32;
    const int nbase = wn * 32;
    const int lq = lane >> 2, lr = lane & 3;
    const int r8 = lane & 7, sel = lane >> 3;
    const int row0 = blockIdx.x * BM;

    const int rA0 = mbase + (sel & 1) * 8 + r8;
    const int rB0 = nbase + (sel >> 1) * 8 + r8;
    const uint32_t eA4 = (uint32_t)(((sel >> 1) ^ r8) << 4);
    const uint32_t eB4 = (uint32_t)(((sel & 1) ^ r8) << 4);
    const uint32_t aoff0 = (uint32_t)rA0 * 256;
    const uint32_t aoff1 = aoff0 + 16 * 256;
    const uint32_t bb0 = wbuf_u + (uint32_t)rB0 * 256;
    const uint32_t bb1 = bb0 + 16 * 256;

    // epilogue store addressing, L<2 grid (row&7 == lq)
    const uint32_t rbase = (uint32_t)(mbase + lq) * 256;
    uint32_t coff[4];
    #pragma unroll
    for (int nt = 0; nt < 4; nt++)
        coff[nt] = ((uint32_t)((((nbase >> 3) + nt) ^ lq) << 4)) + (uint32_t)lr * 4;

    const float m = __ldg(p.mixf);
    const float inv_m = 1.0f - m;
    float Pk[4];
    #pragma unroll
    for (int k = 0; k < 4; k++) Pk[k] = __ldg(p.P + k);

    prefetch_img(wbuf_u, bias_u, 0, 0, tid);

    for (int h = 0; h < 2; h++) {
        // ---- xu -> act buffer 4 (fp16, swizzled) ----
        {
            char* dst = smem + 4 * ACT_B;
            #pragma unroll
            for (int i = tid; i < BM * 16; i += THREADS) {
                const int r = i >> 4, ch = i & 15;
                float4 v0, v1;
                if (ch < 12) {
                    const float* src = p.x + (size_t)(row0 + r) * 96 + ch * 8;
                    v0 = *reinterpret_cast<const float4*>(src);
                    v1 = *reinterpret_cast<const float4*>(src + 4);
                } else {
                    const float* src = p.u + (size_t)(row0 + r) * 32 + (ch - 12) * 8;
                    v0 = *reinterpret_cast<const float4*>(src);
                    v1 = *reinterpret_cast<const float4*>(src + 4);
                }
                __half2 t0 = __floats2half2_rn(v0.x, v0.y);
                __half2 t1 = __floats2half2_rn(v0.z, v0.w);
                __half2 t2 = __floats2half2_rn(v1.x, v1.y);
                __half2 t3 = __floats2half2_rn(v1.z, v1.w);
                uint4 o;
                o.x = *reinterpret_cast<uint32_t*>(&t0);
                o.y = *reinterpret_cast<uint32_t*>(&t1);
                o.z = *reinterpret_cast<uint32_t*>(&t2);
                o.w = *reinterpret_cast<uint32_t*>(&t3);
                *reinterpret_cast<uint4*>(dst + r * 256 + ((ch ^ (r & 7)) << 4)) = o;
            }
        }

        float mix[2][4][4];
        for (int t = 0; t < 15; t++) {
            const int g = h * 15 + t;
            const int L = t / 5, s = t % 5;
            const bool is_main = (s == 4);
            if (s == 0) {
                #pragma unroll
                for (int mt = 0; mt < 2; mt++)
                    #pragma unroll
                    for (int nt = 0; nt < 4; nt++)
                        #pragma unroll
                        for (int c = 0; c < 4; c++) mix[mt][nt][c] = 0.f;
            }

            asm volatile("cp.async.wait_group 0;" ::: "memory");
            __syncthreads();

            const int inb = (L == 0) ? 4 : (is_main ? 4 : s);

            if (L < 2) {
                // ================= L<2: R10 path (2m x 4n grid) =============
                float acc[2][4][4];
                #pragma unroll
                for (int mt = 0; mt < 2; mt++)
                    #pragma unroll
                    for (int nt = 0; nt < 4; nt++)
                        #pragma unroll
                        for (int c = 0; c < 4; c++) acc[mt][nt][c] = 0.f;

                const uint32_t ab0 = sbase + (uint32_t)inb * ACT_B + aoff0;
                const uint32_t ab1 = sbase + (uint32_t)inb * ACT_B + aoff1;
                #pragma unroll
                for (int j = 0; j < 8; j++) {
                    const uint32_t tA = ((uint32_t)(j << 5)) ^ eA4;
                    const uint32_t tB = ((uint32_t)(j << 5)) ^ eB4;
                    uint32_t fa0[4], fa1[4], fb0[4], fb1[4];
                    ldsm4(fa0, ab0 + tA);
                    ldsm4(fa1, ab1 + tA);
                    ldsm4(fb0, bb0 + tB);
                    ldsm4(fb1, bb1 + tB);
                    mma16(acc[0][0], fa0, fb0[0], fb0[1]);
                    mma16(acc[0][1], fa0, fb0[2], fb0[3]);
                    mma16(acc[0][2], fa0, fb1[0], fb1[1]);
                    mma16(acc[0][3], fa0, fb1[2], fb1[3]);
                    mma16(acc[1][0], fa1, fb0[0], fb0[1]);
                    mma16(acc[1][1], fa1, fb0[2], fb0[3]);
                    mma16(acc[1][2], fa1, fb1[0], fb1[1]);
                    mma16(acc[1][3], fa1, fb1[2], fb1[3]);
                }

                float bias[4][2];
                {
                    const float* bs = biasf + (g & 1) * 128;
                    #pragma unroll
                    for (int nt = 0; nt < 4; nt++) {
                        bias[nt][0] = bs[nbase + nt * 8 + lr * 2 + 0];
                        bias[nt][1] = bs[nbase + nt * 8 + lr * 2 + 1];
                    }
                }

                __syncthreads();    // wbuf + act reads done
                prefetch_img(wbuf_u, bias_u, (g + 1) % 30, (g + 1) & 1, tid);

                const float sc = is_main ? inv_m : (m * Pk[s]);
                char* outb = smem + (is_main ? 4 : s) * ACT_B;
                #pragma unroll
                for (int mt = 0; mt < 2; mt++)
                    #pragma unroll
                    for (int nt = 0; nt < 4; nt++)
                        #pragma unroll
                        for (int c2 = 0; c2 < 2; c2++) {
                            const float v0 = acc[mt][nt][c2 * 2 + 0] + bias[nt][0];
                            const float v1 = acc[mt][nt][c2 * 2 + 1] + bias[nt][1];
                            float o0, o1;
                            if (!is_main) {
                                mix[mt][nt][c2 * 2 + 0] = fmaf(sc, v0, mix[mt][nt][c2 * 2 + 0]);
                                mix[mt][nt][c2 * 2 + 1] = fmaf(sc, v1, mix[mt][nt][c2 * 2 + 1]);
                                o0 = v0; o1 = v1;
                            } else {
                                o0 = fmaf(sc, v0, mix[mt][nt][c2 * 2 + 0]);
                                o1 = fmaf(sc, v1, mix[mt][nt][c2 * 2 + 1]);
                            }
                            __half2 hv = __floats2half2_rn(fmaxf(o0, 0.f),
                                                           fmaxf(o1, 0.f));
                            *reinterpret_cast<uint32_t*>(
                                outb + rbase + mt * 4096 + c2 * 2048 + coff[nt])
                                = *reinterpret_cast<uint32_t*>(&hv);
                        }
            } else {
                // ================= L==2: 4m x 2n grid (all warps) ===========
                const int mbase2 = (wid & 3) * 16;
                const int nbase2 = (wid >> 2) * 32;
                const uint32_t aoff2 =
                    (uint32_t)(mbase2 + (sel & 1) * 8 + r8) * 256;
                const uint32_t b20 = wbuf_u +
                    (uint32_t)(nbase2 + (sel >> 1) * 8 + r8) * 256;
                const uint32_t b21 = b20 + 16 * 256;

                float acc2[4][4];
                #pragma unroll
                for (int nt = 0; nt < 4; nt++)
                    #pragma unroll
                    for (int c = 0; c < 4; c++) acc2[nt][c] = 0.f;

                const uint32_t ab = sbase + (uint32_t)inb * ACT_B + aoff2;
                #pragma unroll
                for (int j = 0; j < 8; j++) {
                    const uint32_t tA = ((uint32_t)(j << 5)) ^ eA4;
                    const uint32_t tB = ((uint32_t)(j << 5)) ^ eB4;
                    uint32_t fa[4], fb0[4], fb1[4];
                    ldsm4(fa, ab + tA);
                    ldsm4(fb0, b20 + tB);
                    ldsm4(fb1, b21 + tB);
                    mma16(acc2[0], fa, fb0[0], fb0[1]);
                    mma16(acc2[1], fa, fb0[2], fb0[3]);
                    mma16(acc2[2], fa, fb1[0], fb1[1]);
                    mma16(acc2[3], fa, fb1[2], fb1[3]);
                }

                float bias[4][2];
                {
                    const float* bs = biasf + (g & 1) * 128;
                    #pragma unroll
                    for (int nt = 0; nt < 4; nt++) {
                        bias[nt][0] = bs[nbase2 + nt * 8 + lr * 2 + 0];
                        bias[nt][1] = bs[nbase2 + nt * 8 + lr * 2 + 1];
                    }
                }

                __syncthreads();    // wbuf + act reads done
                prefetch_img(wbuf_u, bias_u, (g + 1) % 30, (g + 1) & 1, tid);

                const float sc = is_main ? inv_m : (m * Pk[s]);
                #pragma unroll
                for (int nt = 0; nt < 4; nt++)
                    #pragma unroll
                    for (int c2 = 0; c2 < 2; c2++) {
                        const float v0 = acc2[nt][c2 * 2 + 0] + bias[nt][0];
                        const float v1 = acc2[nt][c2 * 2 + 1] + bias[nt][1];
                        if (!is_main) {
                            // teacher L2: mix only (ht3 not stored)
                            mix[0][nt][c2 * 2 + 0] = fmaf(sc, v0, mix[0][nt][c2 * 2 + 0]);
                            mix[0][nt][c2 * 2 + 1] = fmaf(sc, v1, mix[0][nt][c2 * 2 + 1]);
                        } else {
                            const float o0 = fmaf(sc, v0, mix[0][nt][c2 * 2 + 0]);
                            const float o1 = fmaf(sc, v1, mix[0][nt][c2 * 2 + 1]);
                            __half2 hv = __floats2half2_rn(fmaxf(o0, 0.f),
                                                           fmaxf(o1, 0.f));
                            const uint32_t rb2 = (uint32_t)(mbase2 + lq) * 256;
                            const uint32_t co2 =
                                ((uint32_t)((((nbase2 >> 3) + nt) ^ lq) << 4)) +
                                (uint32_t)lr * 4;
                            *reinterpret_cast<uint32_t*>(
                                smem + 4 * ACT_B + rb2 + c2 * 2048 + co2)
                                = *reinterpret_cast<uint32_t*>(&hv);
                        }
                    }
            }
        }

        __syncthreads();
        // ---- final layer: out = h3 . W4 + b4 ----
        if (tid < BM) {
            float sum = __ldg(p.b4[h]);
            const float* W4 = p.W4[h];
            const char* hb = smem + 4 * ACT_B;
            #pragma unroll
            for (int k2 = 0; k2 < 64; k2++) {
                const __half hv = *reinterpret_cast<const __half*>(
                    hb + tid * 256 + (((k2 >> 3) ^ (tid & 7)) << 4) + (k2 & 7) * 2);
                sum = fmaf(__half2float(hv), __ldg(W4 + k2), sum);
            }
            p.out[(size_t)h * BATCH + row0 + tid] = sum;
        }
        __syncthreads();
    }
}

extern "C" void kernel_launch(void* const* d_in, const int* in_sizes, int n_in,
                              void* d_out, int out_size) {
    (void)in_sizes; (void)n_in; (void)out_size;
    Params p;
    p.x    = (const float*)d_in[0];
    p.u    = (const float*)d_in[1];
    p.mixf = (const float*)d_in[2];
    p.P    = (const float*)d_in[3];
    for (int h = 0; h < 2; h++) {
        const int base = 4 + h * 8;
        p.W[h][0]  = (const float*)d_in[base + 0];
        p.Bb[h][0] = (const float*)d_in[base + 1];
        p.W[h][1]  = (const float*)d_in[base + 2];
        p.Bb[h][1] = (const float*)d_in[base + 3];
        p.W[h][2]  = (const float*)d_in[base + 4];
        p.Bb[h][2] = (const float*)d_in[base + 5];
        p.W4[h]    = (const float*)d_in[base + 6];
        p.b4[h]    = (const float*)d_in[base + 7];
        const int tbase = 20 + h * 6;
        p.tW[h][0] = (const float*)d_in[tbase + 0];
        p.tb[h][0] = (const float*)d_in[tbase + 1];
        p.tW[h][1] = (const float*)d_in[tbase + 2];
        p.tb[h][1] = (const float*)d_in[tbase + 3];
        p.tW[h][2] = (const float*)d_in[tbase + 4];
        p.tb[h][2] = (const float*)d_in[tbase + 5];
    }
    p.out = (float*)d_out;

    prep_kernel<<<(30 * 2048 + 960 + 255) / 256, 256>>>(p);
    cudaFuncSetAttribute(critic_main,
                         cudaFuncAttributeMaxDynamicSharedMemorySize, SMEM_BYTES);
    critic_main<<<NBLK, THREADS, SMEM_BYTES>>>(p);
}